// round 5
// baseline (speedup 1.0000x reference)
#include <cuda_runtime.h>
#include <math.h>

// Problem constants
#define BATCH   2
#define HW      64
#define NPIX    4096
#define BN      8192
#define DIMQ    64
#define CLD     128
#define KTOK    8
#define FLOW_SZ 1048576       // 2*2*512*512

// ---- device scratch (filled by upsample kernel's prep blocks) ----
__device__ __align__(16) float g_w1t[81 * 64];     // g_w1t[c*64+o] = fte_w1[o*81+c]
__device__ __align__(16) float g_w2t[64 * 64];     // g_w2t[c*64+o] = fte_w2[o*64+c]
__device__ __align__(16) float g_wk_t[64 * 128];   // g_wk_t[d*128+c] = wk[c*64+d]
__device__ __align__(16) float g_wv_t[64 * 128];   // g_wv_t[d*128+c] = wv[c*64+d]

__device__ __forceinline__ float gelu_exact(float x) {
    return 0.5f * x * (1.0f + erff(x * 0.70710678118654752f));
}

__device__ __forceinline__ float samp_map(const float* __restrict__ p, int ix, int iy) {
    if ((unsigned)ix < 64u && (unsigned)iy < 64u) return p[iy * 64 + ix];
    return 0.0f;
}

__device__ __forceinline__ float4 fma4(float s, float4 a, float4 b) {
    return make_float4(fmaf(s, a.x, b.x), fmaf(s, a.y, b.y),
                       fmaf(s, a.z, b.z), fmaf(s, a.w, b.w));
}
__device__ __forceinline__ float4 fma44(float4 m, float4 a, float4 b) {
    return make_float4(fmaf(m.x, a.x, b.x), fmaf(m.y, a.y, b.y),
                       fmaf(m.z, a.z, b.z), fmaf(m.w, a.w, b.w));
}
__device__ __forceinline__ float hsum4(float4 a) {
    return (a.x + a.y) + (a.z + a.w);
}

// Per-warp shared layout. cm rows padded to 132 floats for conflict-free
// j-indexed / h-indexed LDS.128 access (132 % 32 = 4 -> bank rotation).
struct __align__(16) TokSmem {
    float cm[8 * 132];   // padded cost_memory rows
    float tu[8 * 132];   // t[h][c] then reused as u[h][c]
    float corr[96];      // corr[81]; later attn[64]
    float bufA[64];
    float bufB[64];
    float qlin[64];
    float short_s[64];
    float x_s[64];
};

__global__ __launch_bounds__(128) void decoder_kernel(
    const float* __restrict__ cost_maps,
    const float* __restrict__ cost_memory,
    const float* __restrict__ coords1,
    const float* __restrict__ fte_b1,
    const float* __restrict__ fte_b2,
    const float* __restrict__ ln1_g, const float* __restrict__ ln1_b,
    const float* __restrict__ ln2_g, const float* __restrict__ ln2_b,
    const float* __restrict__ wq,  const float* __restrict__ bq,
    const float* __restrict__ bv,
    const float* __restrict__ wp,  const float* __restrict__ bp,
    const float* __restrict__ fw1, const float* __restrict__ fb1,
    const float* __restrict__ fw2, const float* __restrict__ fb2,
    float* __restrict__ out)
{
    __shared__ TokSmem ts[4];
    const int warp = threadIdx.x >> 5;
    const int lane = threadIdx.x & 31;
    const int n    = blockIdx.x * 4 + warp;
    TokSmem& S = ts[warp];

    const int b   = n >> 12;
    const int pix = n & 4095;
    const float cx = coords1[b * 8192 + pix];
    const float cy = coords1[b * 8192 + 4096 + pix];
    const int o0 = lane, o1 = lane + 32;

    // ---- load cost_memory into padded smem rows (coalesced float4) ----
    {
        const float4* src = (const float4*)(cost_memory + (size_t)n * 1024);
        #pragma unroll
        for (int j = 0; j < 8; ++j)
            ((float4*)(S.cm + j * 132))[lane] = src[j * 32 + lane];
    }

    // ---- bilinear correlation sampling: 81 samples ----
    {
        const float* cmap = cost_maps + (size_t)n * 4096;
        for (int s = lane; s < 81; s += 32) {
            int si = s / 9, sj = s - si * 9;
            float px = cx + (float)(si - 4);
            float py = cy + (float)(sj - 4);
            float fx0 = floorf(px), fy0 = floorf(py);
            float wx = px - fx0, wy = py - fy0;
            int ix = (int)fx0, iy = (int)fy0;
            float v00 = samp_map(cmap, ix,     iy);
            float v10 = samp_map(cmap, ix + 1, iy);
            float v01 = samp_map(cmap, ix,     iy + 1);
            float v11 = samp_map(cmap, ix + 1, iy + 1);
            S.corr[s] = v00 * (1.f - wx) * (1.f - wy) + v10 * wx * (1.f - wy)
                      + v01 * (1.f - wx) * wy         + v11 * wx * wy;
        }
    }
    __syncwarp();

    // ---- flow token encoder: q1 = gelu(W1 @ corr + b1) ----
    {
        float a0 = fte_b1[o0], a1 = fte_b1[o1];
        #pragma unroll 3
        for (int c = 0; c < 81; ++c) {
            float cr = S.corr[c];
            a0 = fmaf(cr, g_w1t[c * 64 + o0], a0);
            a1 = fmaf(cr, g_w1t[c * 64 + o1], a1);
        }
        S.bufA[o0] = gelu_exact(a0);
        S.bufA[o1] = gelu_exact(a1);
    }
    __syncwarp();

    // ---- q2 = W2 @ q1 + b2  (= query = short) ----
    float q0 = fte_b2[o0], q1v = fte_b2[o1];
    #pragma unroll 4
    for (int c = 0; c < 64; ++c) {
        float t = S.bufA[c];
        q0  = fmaf(t, g_w2t[c * 64 + o0], q0);
        q1v = fmaf(t, g_w2t[c * 64 + o1], q1v);
    }
    S.short_s[o0] = q0;
    S.short_s[o1] = q1v;

    // ---- layernorm1 + positional encoding ----
    {
        float sm = q0 + q1v;
        #pragma unroll
        for (int off = 16; off; off >>= 1) sm += __shfl_xor_sync(0xffffffffu, sm, off);
        float mean = sm * (1.0f / 64.0f);
        float d0 = q0 - mean, d1 = q1v - mean;
        float vs = d0 * d0 + d1 * d1;
        #pragma unroll
        for (int off = 16; off; off >>= 1) vs += __shfl_xor_sync(0xffffffffu, vs, off);
        float inv = rsqrtf(vs * (1.0f / 64.0f) + 1e-5f);

        float enc0, enc1;
        {
            int r = o0 >> 4, f = o0 & 15;
            float base = (r < 2) ? cx : cy;
            float ang = 3.14f * base * (float)f / 200.0f;
            enc0 = ((r & 1) == 0) ? sinf(ang) : cosf(ang);
        }
        {
            int r = o1 >> 4, f = o1 & 15;
            float base = (r < 2) ? cx : cy;
            float ang = 3.14f * base * (float)f / 200.0f;
            enc1 = ((r & 1) == 0) ? sinf(ang) : cosf(ang);
        }
        S.bufB[o0] = d0 * inv * ln1_g[o0] + ln1_b[o0] + enc0;
        S.bufB[o1] = d1 * inv * ln1_g[o1] + ln1_b[o1] + enc1;
    }
    __syncwarp();

    // ---- q projection ----
    {
        float a0 = bq[o0], a1 = bq[o1];
        #pragma unroll 4
        for (int i = 0; i < 64; ++i) {
            float xv = S.bufB[i];
            a0 = fmaf(xv, wq[i * 64 + o0], a0);
            a1 = fmaf(xv, wq[i * 64 + o1], a1);
        }
        S.qlin[o0] = a0;
        S.qlin[o1] = a1;
    }
    __syncwarp();

    // ---- T: t[h][c] = sum_{e<8} wk[c][h*8+e] * q[h*8+e]  (coalesced wk_t) ----
    {
        const float4* wkt4 = (const float4*)g_wk_t;   // [64][32] float4
        const float4* q4   = (const float4*)S.qlin;   // 16 float4
        #pragma unroll
        for (int h = 0; h < 8; ++h) {
            float4 qa = q4[2 * h], qb = q4[2 * h + 1];
            const float4* w = wkt4 + (h * 8) * 32 + lane;
            float4 acc = make_float4(0.f, 0.f, 0.f, 0.f);
            acc = fma4(qa.x, w[0 * 32], acc);
            acc = fma4(qa.y, w[1 * 32], acc);
            acc = fma4(qa.z, w[2 * 32], acc);
            acc = fma4(qa.w, w[3 * 32], acc);
            acc = fma4(qb.x, w[4 * 32], acc);
            acc = fma4(qb.y, w[5 * 32], acc);
            acc = fma4(qb.z, w[6 * 32], acc);
            acc = fma4(qb.w, w[7 * 32], acc);
            ((float4*)(S.tu + h * 132))[lane] = acc;
        }
    }
    __syncwarp();

    // ---- scores + softmax: s[h][j] = cm[j] . t[h]  (bk cancels in softmax) ----
    {
        int h0 = lane >> 3, jj = lane & 7;
        int h1 = h0 + 4;
        const float4* cmj = (const float4*)(S.cm + jj * 132);
        const float4* t0  = (const float4*)(S.tu + h0 * 132);
        const float4* t1  = (const float4*)(S.tu + h1 * 132);
        float4 a0 = make_float4(0.f, 0.f, 0.f, 0.f);
        float4 a1 = make_float4(0.f, 0.f, 0.f, 0.f);
        #pragma unroll 8
        for (int c4 = 0; c4 < 32; ++c4) {
            float4 m = cmj[c4];
            a0 = fma44(m, t0[c4], a0);
            a1 = fma44(m, t1[c4], a1);
        }
        float s0 = hsum4(a0) * 0.35355339059327373f;
        float s1 = hsum4(a1) * 0.35355339059327373f;
        float m0 = s0, m1 = s1;
        #pragma unroll
        for (int off = 4; off; off >>= 1) {
            m0 = fmaxf(m0, __shfl_xor_sync(0xffffffffu, m0, off));
            m1 = fmaxf(m1, __shfl_xor_sync(0xffffffffu, m1, off));
        }
        float e0 = expf(s0 - m0), e1 = expf(s1 - m1);
        float t0s = e0, t1s = e1;
        #pragma unroll
        for (int off = 4; off; off >>= 1) {
            t0s += __shfl_xor_sync(0xffffffffu, t0s, off);
            t1s += __shfl_xor_sync(0xffffffffu, t1s, off);
        }
        S.corr[h0 * 8 + jj] = e0 / t0s;   // attn weights
        S.corr[h1 * 8 + jj] = e1 / t1s;
    }
    __syncwarp();

    // ---- u[h] = sum_j attn[h][j] * cm[j] ----
    {
        float4 uacc[8];
        #pragma unroll
        for (int h = 0; h < 8; ++h) uacc[h] = make_float4(0.f, 0.f, 0.f, 0.f);
        #pragma unroll
        for (int j = 0; j < 8; ++j) {
            float4 m = ((const float4*)(S.cm + j * 132))[lane];
            #pragma unroll
            for (int h = 0; h < 8; ++h)
                uacc[h] = fma4(S.corr[h * 8 + j], m, uacc[h]);
        }
        __syncwarp();   // all lanes done reading t (scores) before overwrite
        #pragma unroll
        for (int h = 0; h < 8; ++h)
            ((float4*)(S.tu + h * 132))[lane] = uacc[h];
    }
    __syncwarp();

    // ---- out[d] = u[h(d)] . wv[:,d] + bv[d]  (attn rows sum to 1) ----
    {
        int h0 = lane >> 3;
        int h1 = h0 + 4;
        const float4* u0  = (const float4*)(S.tu + h0 * 132);
        const float4* u1  = (const float4*)(S.tu + h1 * 132);
        const float4* wv0 = (const float4*)g_wv_t + (size_t)o0 * 32;
        const float4* wv1 = (const float4*)g_wv_t + (size_t)o1 * 32;
        float4 A0 = make_float4(0.f, 0.f, 0.f, 0.f);
        float4 A1 = make_float4(0.f, 0.f, 0.f, 0.f);
        #pragma unroll 8
        for (int c4 = 0; c4 < 32; ++c4) {
            A0 = fma44(u0[c4], wv0[c4], A0);
            A1 = fma44(u1[c4], wv1[c4], A1);
        }
        S.bufA[o0] = hsum4(A0) + bv[o0];
        S.bufA[o1] = hsum4(A1) + bv[o1];
    }
    __syncwarp();

    // ---- proj: x = concat(out, short) @ wp + bp + short ----
    float x0 = bp[o0], x1 = bp[o1];
    #pragma unroll 4
    for (int i = 0; i < 64; ++i) {
        float oi = S.bufA[i];
        x0 = fmaf(oi, wp[i * 64 + o0], x0);
        x1 = fmaf(oi, wp[i * 64 + o1], x1);
    }
    #pragma unroll 4
    for (int i = 0; i < 64; ++i) {
        float si = S.short_s[i];
        x0 = fmaf(si, wp[(64 + i) * 64 + o0], x0);
        x1 = fmaf(si, wp[(64 + i) * 64 + o1], x1);
    }
    x0 += S.short_s[o0];
    x1 += S.short_s[o1];

    // ---- layernorm2 ----
    {
        float sm = x0 + x1;
        #pragma unroll
        for (int off = 16; off; off >>= 1) sm += __shfl_xor_sync(0xffffffffu, sm, off);
        float mean = sm * (1.0f / 64.0f);
        float d0 = x0 - mean, d1 = x1 - mean;
        float vs = d0 * d0 + d1 * d1;
        #pragma unroll
        for (int off = 16; off; off >>= 1) vs += __shfl_xor_sync(0xffffffffu, vs, off);
        float inv = rsqrtf(vs * (1.0f / 64.0f) + 1e-5f);
        S.bufB[o0] = d0 * inv * ln2_g[o0] + ln2_b[o0];
        S.bufB[o1] = d1 * inv * ln2_g[o1] + ln2_b[o1];
    }
    __syncwarp();

    // ---- FFN hidden ----
    {
        float a0 = fb1[o0], a1 = fb1[o1];
        #pragma unroll 4
        for (int i = 0; i < 64; ++i) {
            float xv = S.bufB[i];
            a0 = fmaf(xv, fw1[i * 64 + o0], a0);
            a1 = fmaf(xv, fw1[i * 64 + o1], a1);
        }
        S.bufA[o0] = gelu_exact(a0);
        S.bufA[o1] = gelu_exact(a1);
    }
    __syncwarp();

    // ---- FFN out + residual ----
    {
        float a0 = fb2[o0], a1 = fb2[o1];
        #pragma unroll 4
        for (int i = 0; i < 64; ++i) {
            float hv = S.bufA[i];
            a0 = fmaf(hv, fw2[i * 64 + o0], a0);
            a1 = fmaf(hv, fw2[i * 64 + o1], a1);
        }
        S.x_s[o0] = x0 + a0;
        S.x_s[o1] = x1 + a1;
    }

    // ---- block-staged transposed writeout ----
    __syncthreads();
    {
        int n0 = blockIdx.x * 4;
        int bb = n0 >> 12;
        int pix0 = n0 & 4095;
        float* cg = out + FLOW_SZ + (size_t)bb * 64 * 4096;
        for (int idx = threadIdx.x; idx < 256; idx += 128) {
            int o = idx >> 2, t = idx & 3;
            cg[o * 4096 + pix0 + t] = ts[t].x_s[o];
        }
    }
}

// ============================================================================
// Convex upsampling; blocks 0..23 transpose FTE weights, blocks 24..87
// transpose wk/wv for the decoder.
// ============================================================================
__global__ __launch_bounds__(256) void upsample_kernel(
    const float* __restrict__ coords1,
    const float* __restrict__ up_mask,
    const float* __restrict__ fte_w1,
    const float* __restrict__ fte_w2,
    const float* __restrict__ wk,
    const float* __restrict__ wv,
    float* __restrict__ out)
{
    __shared__ float slab[576 * 8];
    __shared__ float fl[2][3][10];
    __shared__ float outp[2 * 8 * 64];

    int blk = blockIdx.x;
    int tid = threadIdx.x;

    if (blk < 24) {
        int i = blk * 256 + tid;
        if (i < 81 * 64) {
            int c = i >> 6, o = i & 63;
            g_w1t[i] = fte_w1[o * 81 + c];
        }
        if (i < 64 * 64) {
            int c = i >> 6, o = i & 63;
            g_w2t[i] = fte_w2[o * 64 + c];
        }
    } else if (blk < 88) {
        int i = (blk - 24) * 256 + tid;   // [0, 16384)
        if (i < 8192) {
            int d = i >> 7, c = i & 127;
            g_wk_t[i] = wk[c * 64 + d];
        } else {
            int j = i - 8192;
            int d = j >> 7, c = j & 127;
            g_wv_t[j] = wv[c * 64 + d];
        }
    }

    int b   = blk >> 9;
    int rem = blk & 511;
    int y   = rem >> 3;
    int x0  = (rem & 7) << 3;

    // float4 slab load: 1152 float4 per block
    const float* mbase = up_mask + (size_t)b * 576 * 4096 + y * 64 + x0;
    for (int idx = tid; idx < 1152; idx += 256) {
        int ch = idx >> 1, half = idx & 1;
        ((float4*)slab)[idx] =
            *(const float4*)(mbase + (size_t)ch * 4096 + half * 4);
    }
    if (tid < 60) {
        int c = tid / 30, r2 = tid % 30, r = r2 / 10, cc = r2 % 10;
        int yy = y + r - 1, xx = x0 + cc - 1;
        float v = 0.0f;
        if ((unsigned)yy < 64u && (unsigned)xx < 64u) {
            float coord = coords1[b * 8192 + c * 4096 + yy * 64 + xx];
            v = 8.0f * (coord - (float)(c == 0 ? xx : yy));
        }
        fl[c][r][cc] = v;
    }
    __syncthreads();

    for (int q = tid; q < 512; q += 256) {
        int p  = q & 7;
        int ij = q >> 3;
        int i  = ij >> 3, j = ij & 7;
        float w[9];
        float mx = -1e30f;
        #pragma unroll
        for (int kk = 0; kk < 9; ++kk) {
            w[kk] = slab[(kk * 64 + ij) * 8 + p];
            mx = fmaxf(mx, w[kk]);
        }
        float s = 0.f;
        #pragma unroll
        for (int kk = 0; kk < 9; ++kk) { w[kk] = __expf(w[kk] - mx); s += w[kk]; }
        float inv = 1.0f / s;
        float u0 = 0.f, u1 = 0.f;
        #pragma unroll
        for (int kk = 0; kk < 9; ++kk) {
            int dy = kk / 3, dx = kk - dy * 3;
            u0 = fmaf(w[kk], fl[0][dy][p + dx], u0);
            u1 = fmaf(w[kk], fl[1][dy][p + dx], u1);
        }
        int col = p * 8 + j;
        outp[(0 * 8 + i) * 64 + col] = u0 * inv;
        outp[(1 * 8 + i) * 64 + col] = u1 * inv;
    }
    __syncthreads();

    float* obase = out + (size_t)b * 2 * 512 * 512 + (size_t)(8 * y) * 512 + 8 * x0;
    for (int idx = tid; idx < 1024; idx += 256) {
        int c = idx >> 9, rest = idx & 511;
        int i = rest >> 6, col = rest & 63;
        obase[(size_t)c * 512 * 512 + i * 512 + col] = outp[(c * 8 + i) * 64 + col];
    }
}

extern "C" void kernel_launch(void* const* d_in, const int* in_sizes, int n_in,
                              void* d_out, int out_size) {
    const float* cost_maps   = (const float*)d_in[0];
    const float* cost_memory = (const float*)d_in[1];
    const float* coords1     = (const float*)d_in[2];
    const float* up_mask     = (const float*)d_in[3];
    const float* fte_w1      = (const float*)d_in[4];
    const float* fte_b1      = (const float*)d_in[5];
    const float* fte_w2      = (const float*)d_in[6];
    const float* fte_b2      = (const float*)d_in[7];
    const float* ln1_g       = (const float*)d_in[8];
    const float* ln1_b       = (const float*)d_in[9];
    const float* ln2_g       = (const float*)d_in[10];
    const float* ln2_b       = (const float*)d_in[11];
    const float* wq          = (const float*)d_in[12];
    const float* bq          = (const float*)d_in[13];
    const float* wk          = (const float*)d_in[14];
    const float* bv          = (const float*)d_in[17];
    const float* wv          = (const float*)d_in[16];
    const float* wp          = (const float*)d_in[18];
    const float* bp          = (const float*)d_in[19];
    const float* fw1         = (const float*)d_in[20];
    const float* fb1         = (const float*)d_in[21];
    const float* fw2         = (const float*)d_in[22];
    const float* fb2         = (const float*)d_in[23];
    float* out = (float*)d_out;

    upsample_kernel<<<1024, 256>>>(coords1, up_mask, fte_w1, fte_w2, wk, wv, out);
    decoder_kernel<<<2048, 128>>>(cost_maps, cost_memory, coords1,
                                  fte_b1, fte_b2,
                                  ln1_g, ln1_b, ln2_g, ln2_b,
                                  wq, bq, bv, wp, bp,
                                  fw1, fb1, fw2, fb2, out);
}

// round 6
// speedup vs baseline: 2.6106x; 2.6106x over previous
#include <cuda_runtime.h>
#include <math.h>

#define FLOW_SZ 1048576       // 2*2*512*512

// ---- device scratch (filled by upsample kernel's prep blocks) ----
__device__ __align__(16) float g_w1t[81 * 64];     // g_w1t[c*64+o] = fte_w1[o*81+c]
__device__ __align__(16) float g_w2t[64 * 64];     // g_w2t[c*64+o] = fte_w2[o*64+c]
__device__ __align__(16) float g_wk_t[64 * 128];   // g_wk_t[d*128+c] = wk[c*64+d]

__device__ __forceinline__ float gelu_exact(float x) {
    return 0.5f * x * (1.0f + erff(x * 0.70710678118654752f));
}

__device__ __forceinline__ float samp_map(const float* __restrict__ p, int ix, int iy) {
    if ((unsigned)ix < 64u && (unsigned)iy < 64u) return p[iy * 64 + ix];
    return 0.0f;
}

__device__ __forceinline__ float4 fma4(float s, float4 a, float4 b) {
    return make_float4(fmaf(s, a.x, b.x), fmaf(s, a.y, b.y),
                       fmaf(s, a.z, b.z), fmaf(s, a.w, b.w));
}
__device__ __forceinline__ float hsum4(float4 a) {
    return (a.x + a.y) + (a.z + a.w);
}

__device__ __forceinline__ float posenc(float cx, float cy, int o) {
    int r = o >> 4, f = o & 15;
    float base = (r < 2) ? cx : cy;
    float ang = 3.14f * base * (float)f / 200.0f;
    return ((r & 1) == 0) ? sinf(ang) : cosf(ang);
}

// Dual-token matmul: out[o] = sum_c act[t][c] * w[c*64+o], o0=2*lane, o1=2*lane+1.
// Weight rows loaded once (LDG.64), shared across both tokens; activations as
// float4 LDS broadcasts (1 per 4 rows per token). ROWS % 4 == 0.
template <int ROWS>
__device__ __forceinline__ void mm2(const float* __restrict__ a0,
                                    const float* __restrict__ a1,
                                    const float* __restrict__ w,
                                    int l, float2& r0, float2& r1)
{
    const float* wl = w + 2 * l;
    #pragma unroll 4
    for (int c = 0; c < ROWS; c += 4) {
        float4 x0 = *(const float4*)(a0 + c);
        float4 x1 = *(const float4*)(a1 + c);
        float2 wa = *(const float2*)(wl + (c + 0) * 64);
        float2 wb = *(const float2*)(wl + (c + 1) * 64);
        float2 wc = *(const float2*)(wl + (c + 2) * 64);
        float2 wd = *(const float2*)(wl + (c + 3) * 64);
        r0.x = fmaf(x0.x, wa.x, r0.x); r0.y = fmaf(x0.x, wa.y, r0.y);
        r1.x = fmaf(x1.x, wa.x, r1.x); r1.y = fmaf(x1.x, wa.y, r1.y);
        r0.x = fmaf(x0.y, wb.x, r0.x); r0.y = fmaf(x0.y, wb.y, r0.y);
        r1.x = fmaf(x1.y, wb.x, r1.x); r1.y = fmaf(x1.y, wb.y, r1.y);
        r0.x = fmaf(x0.z, wc.x, r0.x); r0.y = fmaf(x0.z, wc.y, r0.y);
        r1.x = fmaf(x1.z, wc.x, r1.x); r1.y = fmaf(x1.z, wc.y, r1.y);
        r0.x = fmaf(x0.w, wd.x, r0.x); r0.y = fmaf(x0.w, wd.y, r0.y);
        r1.x = fmaf(x1.w, wd.x, r1.x); r1.y = fmaf(x1.w, wd.y, r1.y);
    }
}

// Per-warp shared state for 2 tokens. Rows of cm/tu padded to 132 floats so the
// 8-row-indexed accesses in scores/u/out land on disjoint bank groups.
struct __align__(16) WarpSmem {
    float cm[2][1056];    // 8 x 132 cost_memory rows
    float tu[2][1056];    // t[h][c] then overwritten by u[h][c]
    float corr[2][88];    // 81 correlation values
    float attn[2][64];    // softmaxed attention
    float qlin[2][64];
    float A[2][64];       // gelu(fte1) -> attn_out -> ffn hidden
    float B[2][64];       // normed (+enc) vectors
    float sh[2][64];      // short (residual)
    float xs[2][64];      // final
};

__global__ __launch_bounds__(64) void decoder_kernel(
    const float* __restrict__ cost_maps,
    const float* __restrict__ cost_memory,
    const float* __restrict__ coords1,
    const float* __restrict__ fte_b1,
    const float* __restrict__ fte_b2,
    const float* __restrict__ ln1_g, const float* __restrict__ ln1_b,
    const float* __restrict__ ln2_g, const float* __restrict__ ln2_b,
    const float* __restrict__ wq,  const float* __restrict__ bq,
    const float* __restrict__ wv,  const float* __restrict__ bv,
    const float* __restrict__ wp,  const float* __restrict__ bp,
    const float* __restrict__ fw1, const float* __restrict__ fb1,
    const float* __restrict__ fw2, const float* __restrict__ fb2,
    float* __restrict__ out)
{
    __shared__ WarpSmem ts[2];
    const int warp = threadIdx.x >> 5;
    const int lane = threadIdx.x & 31;
    const int l = lane;
    const int n0 = blockIdx.x * 4 + warp * 2;   // tokens n0, n0+1
    WarpSmem& S = ts[warp];

    const int b = n0 >> 12;
    const int pix0 = n0 & 4095;
    const float cx0 = coords1[b * 8192 + pix0];
    const float cy0 = coords1[b * 8192 + 4096 + pix0];
    const float cx1 = coords1[b * 8192 + pix0 + 1];
    const float cy1 = coords1[b * 8192 + 4096 + pix0 + 1];
    const int o0 = 2 * l, o1 = 2 * l + 1;

    // ---- phase 0: load cost_memory rows into padded smem ----
    #pragma unroll
    for (int t = 0; t < 2; ++t) {
        const float4* src = (const float4*)(cost_memory + (size_t)(n0 + t) * 1024);
        #pragma unroll
        for (int r = 0; r < 8; ++r)
            ((float4*)&S.cm[t][r * 132])[l] = src[r * 32 + l];
    }

    // ---- phase 1: bilinear correlation sampling (81 per token) ----
    #pragma unroll
    for (int t = 0; t < 2; ++t) {
        const float* cmap = cost_maps + (size_t)(n0 + t) * 4096;
        const float cx = t ? cx1 : cx0;
        const float cy = t ? cy1 : cy0;
        for (int s = l; s < 81; s += 32) {
            int si = s / 9, sj = s - si * 9;
            float px = cx + (float)(si - 4);
            float py = cy + (float)(sj - 4);
            float fx0 = floorf(px), fy0 = floorf(py);
            float wx = px - fx0, wy = py - fy0;
            int ix = (int)fx0, iy = (int)fy0;
            float v00 = samp_map(cmap, ix,     iy);
            float v10 = samp_map(cmap, ix + 1, iy);
            float v01 = samp_map(cmap, ix,     iy + 1);
            float v11 = samp_map(cmap, ix + 1, iy + 1);
            S.corr[t][s] = v00 * (1.f - wx) * (1.f - wy) + v10 * wx * (1.f - wy)
                         + v01 * (1.f - wx) * wy         + v11 * wx * wy;
        }
    }
    __syncwarp();

    // ---- phase 2: FTE1 = gelu(corr @ W1 + b1) ----
    {
        float2 bb2 = *(const float2*)(fte_b1 + o0);
        float2 r0 = bb2, r1 = bb2;
        mm2<80>(S.corr[0], S.corr[1], g_w1t, l, r0, r1);
        float c80w0 = g_w1t[80 * 64 + o0], c80w1 = g_w1t[80 * 64 + o1];
        float a80_0 = S.corr[0][80], a80_1 = S.corr[1][80];
        r0.x = fmaf(a80_0, c80w0, r0.x); r0.y = fmaf(a80_0, c80w1, r0.y);
        r1.x = fmaf(a80_1, c80w0, r1.x); r1.y = fmaf(a80_1, c80w1, r1.y);
        *(float2*)&S.A[0][o0] = make_float2(gelu_exact(r0.x), gelu_exact(r0.y));
        *(float2*)&S.A[1][o0] = make_float2(gelu_exact(r1.x), gelu_exact(r1.y));
    }
    __syncwarp();

    // ---- phase 3: query = A @ W2 + b2 (= short) ----
    float2 q0, q1;
    {
        float2 bb2 = *(const float2*)(fte_b2 + o0);
        q0 = bb2; q1 = bb2;
        mm2<64>(S.A[0], S.A[1], g_w2t, l, q0, q1);
        *(float2*)&S.sh[0][o0] = q0;
        *(float2*)&S.sh[1][o0] = q1;
    }

    // ---- phase 4: layernorm1 + positional encoding ----
    {
        float s0 = q0.x + q0.y, s1 = q1.x + q1.y;
        #pragma unroll
        for (int off = 16; off; off >>= 1) {
            s0 += __shfl_xor_sync(0xffffffffu, s0, off);
            s1 += __shfl_xor_sync(0xffffffffu, s1, off);
        }
        float m0 = s0 * (1.f / 64.f), m1 = s1 * (1.f / 64.f);
        float d00 = q0.x - m0, d01 = q0.y - m0;
        float d10 = q1.x - m1, d11 = q1.y - m1;
        float v0 = d00 * d00 + d01 * d01, v1 = d10 * d10 + d11 * d11;
        #pragma unroll
        for (int off = 16; off; off >>= 1) {
            v0 += __shfl_xor_sync(0xffffffffu, v0, off);
            v1 += __shfl_xor_sync(0xffffffffu, v1, off);
        }
        float i0 = rsqrtf(v0 * (1.f / 64.f) + 1e-5f);
        float i1 = rsqrtf(v1 * (1.f / 64.f) + 1e-5f);
        float2 g2 = *(const float2*)(ln1_g + o0);
        float2 b2v = *(const float2*)(ln1_b + o0);
        float e00 = posenc(cx0, cy0, o0), e01 = posenc(cx0, cy0, o1);
        float e10 = posenc(cx1, cy1, o0), e11 = posenc(cx1, cy1, o1);
        *(float2*)&S.B[0][o0] = make_float2(d00 * i0 * g2.x + b2v.x + e00,
                                            d01 * i0 * g2.y + b2v.y + e01);
        *(float2*)&S.B[1][o0] = make_float2(d10 * i1 * g2.x + b2v.x + e10,
                                            d11 * i1 * g2.y + b2v.y + e11);
    }
    __syncwarp();

    // ---- phase 5: qlin = B @ wq + bq ----
    {
        float2 bb2 = *(const float2*)(bq + o0);
        float2 r0 = bb2, r1 = bb2;
        mm2<64>(S.B[0], S.B[1], wq, l, r0, r1);
        *(float2*)&S.qlin[0][o0] = r0;
        *(float2*)&S.qlin[1][o0] = r1;
    }
    __syncwarp();

    // ---- phase 6: T: t[h][c] = sum_e wk_t[h*8+e][c] * q[h*8+e]  (wk shared) ----
    #pragma unroll
    for (int h = 0; h < 8; ++h) {
        float qa0[8], qa1[8];
        *(float4*)&qa0[0] = *(const float4*)&S.qlin[0][h * 8];
        *(float4*)&qa0[4] = *(const float4*)&S.qlin[0][h * 8 + 4];
        *(float4*)&qa1[0] = *(const float4*)&S.qlin[1][h * 8];
        *(float4*)&qa1[4] = *(const float4*)&S.qlin[1][h * 8 + 4];
        const float* wbase = g_wk_t + (size_t)(h * 8) * 128 + 4 * l;
        float4 acc0 = make_float4(0.f, 0.f, 0.f, 0.f);
        float4 acc1 = make_float4(0.f, 0.f, 0.f, 0.f);
        #pragma unroll
        for (int e = 0; e < 8; ++e) {
            float4 w = *(const float4*)(wbase + e * 128);
            acc0 = fma4(qa0[e], w, acc0);
            acc1 = fma4(qa1[e], w, acc1);
        }
        *(float4*)&S.tu[0][h * 132 + 4 * l] = acc0;
        *(float4*)&S.tu[1][h * 132 + 4 * l] = acc1;
    }
    __syncwarp();

    // ---- phase 7: scores + softmax (bk cancels) ----
    {
        int h0 = l >> 3, j = l & 7, h1 = h0 + 4;
        const float4* cm0 = (const float4*)&S.cm[0][j * 132];
        const float4* cm1 = (const float4*)&S.cm[1][j * 132];
        const float4* ta0 = (const float4*)&S.tu[0][h0 * 132];
        const float4* tb0 = (const float4*)&S.tu[0][h1 * 132];
        const float4* ta1 = (const float4*)&S.tu[1][h0 * 132];
        const float4* tb1 = (const float4*)&S.tu[1][h1 * 132];
        float4 A00 = make_float4(0.f, 0.f, 0.f, 0.f), A01 = A00, A10 = A00, A11 = A00;
        #pragma unroll 8
        for (int c4 = 0; c4 < 32; ++c4) {
            float4 m0 = cm0[c4], m1 = cm1[c4];
            float4 x00 = ta0[c4], x01 = tb0[c4];
            float4 x10 = ta1[c4], x11 = tb1[c4];
            A00.x = fmaf(m0.x, x00.x, A00.x); A00.y = fmaf(m0.y, x00.y, A00.y);
            A00.z = fmaf(m0.z, x00.z, A00.z); A00.w = fmaf(m0.w, x00.w, A00.w);
            A01.x = fmaf(m0.x, x01.x, A01.x); A01.y = fmaf(m0.y, x01.y, A01.y);
            A01.z = fmaf(m0.z, x01.z, A01.z); A01.w = fmaf(m0.w, x01.w, A01.w);
            A10.x = fmaf(m1.x, x10.x, A10.x); A10.y = fmaf(m1.y, x10.y, A10.y);
            A10.z = fmaf(m1.z, x10.z, A10.z); A10.w = fmaf(m1.w, x10.w, A10.w);
            A11.x = fmaf(m1.x, x11.x, A11.x); A11.y = fmaf(m1.y, x11.y, A11.y);
            A11.z = fmaf(m1.z, x11.z, A11.z); A11.w = fmaf(m1.w, x11.w, A11.w);
        }
        const float scale = 0.35355339059327373f;
        float s00 = hsum4(A00) * scale, s01 = hsum4(A01) * scale;
        float s10 = hsum4(A10) * scale, s11 = hsum4(A11) * scale;
        float m00 = s00, m01 = s01, m10 = s10, m11 = s11;
        #pragma unroll
        for (int off = 4; off; off >>= 1) {
            m00 = fmaxf(m00, __shfl_xor_sync(0xffffffffu, m00, off));
            m01 = fmaxf(m01, __shfl_xor_sync(0xffffffffu, m01, off));
            m10 = fmaxf(m10, __shfl_xor_sync(0xffffffffu, m10, off));
            m11 = fmaxf(m11, __shfl_xor_sync(0xffffffffu, m11, off));
        }
        float e00 = expf(s00 - m00), e01 = expf(s01 - m01);
        float e10 = expf(s10 - m10), e11 = expf(s11 - m11);
        float t00 = e00, t01 = e01, t10 = e10, t11 = e11;
        #pragma unroll
        for (int off = 4; off; off >>= 1) {
            t00 += __shfl_xor_sync(0xffffffffu, t00, off);
            t01 += __shfl_xor_sync(0xffffffffu, t01, off);
            t10 += __shfl_xor_sync(0xffffffffu, t10, off);
            t11 += __shfl_xor_sync(0xffffffffu, t11, off);
        }
        S.attn[0][h0 * 8 + j] = e00 / t00;
        S.attn[0][h1 * 8 + j] = e01 / t01;
        S.attn[1][h0 * 8 + j] = e10 / t10;
        S.attn[1][h1 * 8 + j] = e11 / t11;
    }
    __syncwarp();

    // ---- phase 8: u[h] = sum_j attn[h][j] * cm[j]  (overwrites tu) ----
    #pragma unroll
    for (int t = 0; t < 2; ++t) {
        float4 uacc[8];
        #pragma unroll
        for (int h = 0; h < 8; ++h) uacc[h] = make_float4(0.f, 0.f, 0.f, 0.f);
        #pragma unroll
        for (int j = 0; j < 8; ++j) {
            float4 m = *(const float4*)&S.cm[t][j * 132 + 4 * l];
            #pragma unroll
            for (int h = 0; h < 8; ++h)
                uacc[h] = fma4(S.attn[t][h * 8 + j], m, uacc[h]);
        }
        #pragma unroll
        for (int h = 0; h < 8; ++h)
            *(float4*)&S.tu[t][h * 132 + 4 * l] = uacc[h];
    }
    __syncwarp();

    // ---- phase 9: out = u @ wv + bv  (wv original layout, coalesced) ----
    {
        float2 bb2 = *(const float2*)(bv + o0);
        float2 r0 = bb2, r1 = bb2;
        int h = l >> 2;   // head of both o0 and o1
        mm2<128>(&S.tu[0][h * 132], &S.tu[1][h * 132], wv, l, r0, r1);
        *(float2*)&S.A[0][o0] = r0;
        *(float2*)&S.A[1][o0] = r1;
    }
    __syncwarp();

    // ---- phase 10: x = concat(out, short) @ wp + bp + short ----
    float2 x0, x1;
    {
        float2 bb2 = *(const float2*)(bp + o0);
        x0 = bb2; x1 = bb2;
        mm2<64>(S.A[0], S.A[1], wp, l, x0, x1);
        mm2<64>(S.sh[0], S.sh[1], wp + 64 * 64, l, x0, x1);
        float2 sh0 = *(const float2*)&S.sh[0][o0];
        float2 sh1 = *(const float2*)&S.sh[1][o0];
        x0.x += sh0.x; x0.y += sh0.y;
        x1.x += sh1.x; x1.y += sh1.y;
    }

    // ---- phase 11: layernorm2 ----
    {
        float s0 = x0.x + x0.y, s1 = x1.x + x1.y;
        #pragma unroll
        for (int off = 16; off; off >>= 1) {
            s0 += __shfl_xor_sync(0xffffffffu, s0, off);
            s1 += __shfl_xor_sync(0xffffffffu, s1, off);
        }
        float m0 = s0 * (1.f / 64.f), m1 = s1 * (1.f / 64.f);
        float d00 = x0.x - m0, d01 = x0.y - m0;
        float d10 = x1.x - m1, d11 = x1.y - m1;
        float v0 = d00 * d00 + d01 * d01, v1 = d10 * d10 + d11 * d11;
        #pragma unroll
        for (int off = 16; off; off >>= 1) {
            v0 += __shfl_xor_sync(0xffffffffu, v0, off);
            v1 += __shfl_xor_sync(0xffffffffu, v1, off);
        }
        float i0 = rsqrtf(v0 * (1.f / 64.f) + 1e-5f);
        float i1 = rsqrtf(v1 * (1.f / 64.f) + 1e-5f);
        float2 g2 = *(const float2*)(ln2_g + o0);
        float2 b2v = *(const float2*)(ln2_b + o0);
        *(float2*)&S.B[0][o0] = make_float2(d00 * i0 * g2.x + b2v.x,
                                            d01 * i0 * g2.y + b2v.y);
        *(float2*)&S.B[1][o0] = make_float2(d10 * i1 * g2.x + b2v.x,
                                            d11 * i1 * g2.y + b2v.y);
    }
    __syncwarp();

    // ---- phase 12: FFN hidden ----
    {
        float2 bb2 = *(const float2*)(fb1 + o0);
        float2 r0 = bb2, r1 = bb2;
        mm2<64>(S.B[0], S.B[1], fw1, l, r0, r1);
        *(float2*)&S.A[0][o0] = make_float2(gelu_exact(r0.x), gelu_exact(r0.y));
        *(float2*)&S.A[1][o0] = make_float2(gelu_exact(r1.x), gelu_exact(r1.y));
    }
    __syncwarp();

    // ---- phase 13: FFN out + residual ----
    {
        float2 bb2 = *(const float2*)(fb2 + o0);
        float2 r0 = bb2, r1 = bb2;
        mm2<64>(S.A[0], S.A[1], fw2, l, r0, r1);
        *(float2*)&S.xs[0][o0] = make_float2(x0.x + r0.x, x0.y + r0.y);
        *(float2*)&S.xs[1][o0] = make_float2(x1.x + r1.x, x1.y + r1.y);
    }

    // ---- phase 14: block-staged transposed writeout ----
    __syncthreads();
    {
        int nb = blockIdx.x * 4;
        int bb = nb >> 12;
        int px = nb & 4095;
        float* cg = out + FLOW_SZ + (size_t)bb * 64 * 4096;
        for (int idx = threadIdx.x; idx < 256; idx += 64) {
            int o = idx >> 2, t = idx & 3;
            cg[o * 4096 + px + t] = ts[t >> 1].xs[t & 1][o];
        }
    }
}

// ============================================================================
// Convex upsampling; blocks 0..23 transpose FTE weights, blocks 24..55
// transpose wk for the decoder's T step.
// ============================================================================
__global__ __launch_bounds__(256) void upsample_kernel(
    const float* __restrict__ coords1,
    const float* __restrict__ up_mask,
    const float* __restrict__ fte_w1,
    const float* __restrict__ fte_w2,
    const float* __restrict__ wk,
    float* __restrict__ out)
{
    __shared__ float slab[576 * 8];
    __shared__ float fl[2][3][10];
    __shared__ float outp[2 * 8 * 64];

    int blk = blockIdx.x;
    int tid = threadIdx.x;

    if (blk < 24) {
        int i = blk * 256 + tid;
        if (i < 81 * 64) {
            int c = i >> 6, o = i & 63;
            g_w1t[i] = fte_w1[o * 81 + c];
        }
        if (i < 64 * 64) {
            int c = i >> 6, o = i & 63;
            g_w2t[i] = fte_w2[o * 64 + c];
        }
    } else if (blk < 56) {
        int i = (blk - 24) * 256 + tid;   // [0, 8192)
        int d = i >> 7, c = i & 127;
        g_wk_t[i] = wk[c * 64 + d];
    }

    int b   = blk >> 9;
    int rem = blk & 511;
    int y   = rem >> 3;
    int x0  = (rem & 7) << 3;

    const float* mbase = up_mask + (size_t)b * 576 * 4096 + y * 64 + x0;
    for (int idx = tid; idx < 1152; idx += 256) {
        int ch = idx >> 1, half = idx & 1;
        ((float4*)slab)[idx] =
            *(const float4*)(mbase + (size_t)ch * 4096 + half * 4);
    }
    if (tid < 60) {
        int c = tid / 30, r2 = tid % 30, r = r2 / 10, cc = r2 % 10;
        int yy = y + r - 1, xx = x0 + cc - 1;
        float v = 0.0f;
        if ((unsigned)yy < 64u && (unsigned)xx < 64u) {
            float coord = coords1[b * 8192 + c * 4096 + yy * 64 + xx];
            v = 8.0f * (coord - (float)(c == 0 ? xx : yy));
        }
        fl[c][r][cc] = v;
    }
    __syncthreads();

    for (int q = tid; q < 512; q += 256) {
        int p  = q & 7;
        int ij = q >> 3;
        int i  = ij >> 3, j = ij & 7;
        float w[9];
        float mx = -1e30f;
        #pragma unroll
        for (int kk = 0; kk < 9; ++kk) {
            w[kk] = slab[(kk * 64 + ij) * 8 + p];
            mx = fmaxf(mx, w[kk]);
        }
        float s = 0.f;
        #pragma unroll
        for (int kk = 0; kk < 9; ++kk) { w[kk] = __expf(w[kk] - mx); s += w[kk]; }
        float inv = 1.0f / s;
        float u0 = 0.f, u1 = 0.f;
        #pragma unroll
        for (int kk = 0; kk < 9; ++kk) {
            int dy = kk / 3, dx = kk - dy * 3;
            u0 = fmaf(w[kk], fl[0][dy][p + dx], u0);
            u1 = fmaf(w[kk], fl[1][dy][p + dx], u1);
        }
        int col = p * 8 + j;
        outp[(0 * 8 + i) * 64 + col] = u0 * inv;
        outp[(1 * 8 + i) * 64 + col] = u1 * inv;
    }
    __syncthreads();

    float* obase = out + (size_t)b * 2 * 512 * 512 + (size_t)(8 * y) * 512 + 8 * x0;
    for (int idx = tid; idx < 1024; idx += 256) {
        int c = idx >> 9, rest = idx & 511;
        int i = rest >> 6, col = rest & 63;
        obase[(size_t)c * 512 * 512 + i * 512 + col] = outp[(c * 8 + i) * 64 + col];
    }
}

extern "C" void kernel_launch(void* const* d_in, const int* in_sizes, int n_in,
                              void* d_out, int out_size) {
    const float* cost_maps   = (const float*)d_in[0];
    const float* cost_memory = (const float*)d_in[1];
    const float* coords1     = (const float*)d_in[2];
    const float* up_mask     = (const float*)d_in[3];
    const float* fte_w1      = (const float*)d_in[4];
    const float* fte_b1      = (const float*)d_in[5];
    const float* fte_w2      = (const float*)d_in[6];
    const float* fte_b2      = (const float*)d_in[7];
    const float* ln1_g       = (const float*)d_in[8];
    const float* ln1_b       = (const float*)d_in[9];
    const float* ln2_g       = (const float*)d_in[10];
    const float* ln2_b       = (const float*)d_in[11];
    const float* wq          = (const float*)d_in[12];
    const float* bq          = (const float*)d_in[13];
    const float* wk          = (const float*)d_in[14];
    const float* wv          = (const float*)d_in[16];
    const float* bv          = (const float*)d_in[17];
    const float* wp          = (const float*)d_in[18];
    const float* bp          = (const float*)d_in[19];
    const float* fw1         = (const float*)d_in[20];
    const float* fb1         = (const float*)d_in[21];
    const float* fw2         = (const float*)d_in[22];
    const float* fb2         = (const float*)d_in[23];
    float* out = (float*)d_out;

    upsample_kernel<<<1024, 256>>>(coords1, up_mask, fte_w1, fte_w2, wk, out);
    decoder_kernel<<<2048, 64>>>(cost_maps, cost_memory, coords1,
                                 fte_b1, fte_b2,
                                 ln1_g, ln1_b, ln2_g, ln2_b,
                                 wq, bq, wv, bv, wp, bp,
                                 fw1, fb1, fw2, fb2, out);
}